// round 4
// baseline (speedup 1.0000x reference)
#include <cuda_runtime.h>
#include <math.h>

#define SLEN 2048
#define BSZ 4
#define DM 1024
#define NH 16
#define DH 64
#define NQKVB 3088          // NH*(3*DH+1)
#define M_ROWS 8192         // SLEN*BSZ
#define EPSF 1e-5f
#define SCALEF 0.125f       // 1/sqrt(64)

// ---------------- scratch (static device globals; no allocation) ----------------
// g_qkvb doubles as the output-projection result buffer (qkvb is dead after split).
__device__ float g_qkvb[M_ROWS * NQKVB];     // [m][3088]; later: attn [m][1024]
__device__ float g_q[64 * SLEN * DH];        // [b*16+h][l][d]
__device__ float g_k[64 * SLEN * DH];
__device__ float g_v[64 * SLEN * DH];
__device__ float g_beta[64 * SLEN];
__device__ float g_lo[M_ROWS * DM];          // layer_out in [l][b][h*d] layout

// ---------------- fp32 GEMM: C[m][n] = sum_k A[m][k] * B[n][k] ----------------
// BM=128, BN=64, BK=16, 256 threads, thread tile 8x4, register-prefetch
// double buffering on the k loop. M multiple of 128, K multiple of 16; N guarded.
__device__ __forceinline__ void gemm_abt_128x64(const float* __restrict__ A,
                                                const float* __restrict__ B,
                                                float* __restrict__ C,
                                                int N, int K) {
    __shared__ float As[16][132];
    __shared__ float Bs[16][68];
    const int tid = threadIdx.x;
    const int bm = blockIdx.y * 128;
    const int bn = blockIdx.x * 64;
    const int lr = tid >> 2;          // 0..63
    const int lk = (tid & 3) << 2;    // 0,4,8,12
    const int ty = tid >> 4;          // 0..15 -> 8 rows
    const int tx = tid & 15;          // 0..15 -> 4 cols

    const float* pa0 = A + (size_t)(bm + lr) * K + lk;
    const float* pa1 = A + (size_t)(bm + lr + 64) * K + lk;
    const int nb = bn + lr;
    const float* pb = B + (size_t)(nb < N ? nb : 0) * K + lk;
    const bool bvalid = (nb < N);

    float acc[8][4];
#pragma unroll
    for (int i = 0; i < 8; i++)
#pragma unroll
        for (int j = 0; j < 4; j++) acc[i][j] = 0.f;

    // prefetch tile 0 into registers
    float4 a0 = *(const float4*)(pa0);
    float4 a1 = *(const float4*)(pa1);
    float4 bv = make_float4(0.f, 0.f, 0.f, 0.f);
    if (bvalid) bv = *(const float4*)(pb);

    for (int k0 = 0; k0 < K; k0 += 16) {
        // commit prefetched tile to SMEM
        As[lk + 0][lr] = a0.x; As[lk + 1][lr] = a0.y;
        As[lk + 2][lr] = a0.z; As[lk + 3][lr] = a0.w;
        As[lk + 0][lr + 64] = a1.x; As[lk + 1][lr + 64] = a1.y;
        As[lk + 2][lr + 64] = a1.z; As[lk + 3][lr + 64] = a1.w;
        Bs[lk + 0][lr] = bv.x; Bs[lk + 1][lr] = bv.y;
        Bs[lk + 2][lr] = bv.z; Bs[lk + 3][lr] = bv.w;
        __syncthreads();

        // prefetch next tile (overlaps with FFMA block below)
        if (k0 + 16 < K) {
            a0 = *(const float4*)(pa0 + k0 + 16);
            a1 = *(const float4*)(pa1 + k0 + 16);
            if (bvalid) bv = *(const float4*)(pb + k0 + 16);
        }

#pragma unroll
        for (int kk = 0; kk < 16; kk++) {
            float4 af0 = *(const float4*)&As[kk][ty * 8];
            float4 af1 = *(const float4*)&As[kk][ty * 8 + 4];
            float4 bf  = *(const float4*)&Bs[kk][tx * 4];
            float a[8] = {af0.x, af0.y, af0.z, af0.w, af1.x, af1.y, af1.z, af1.w};
            float b[4] = {bf.x, bf.y, bf.z, bf.w};
#pragma unroll
            for (int i = 0; i < 8; i++)
#pragma unroll
                for (int j = 0; j < 4; j++) acc[i][j] = fmaf(a[i], b[j], acc[i][j]);
        }
        __syncthreads();
    }

#pragma unroll
    for (int i = 0; i < 8; i++) {
        int row = bm + ty * 8 + i;
        int col = bn + tx * 4;
        if (col + 3 < N) {
            float4 o = make_float4(acc[i][0], acc[i][1], acc[i][2], acc[i][3]);
            *(float4*)&C[(size_t)row * N + col] = o;
        } else {
#pragma unroll
            for (int j = 0; j < 4; j++)
                if (col + j < N) C[(size_t)row * N + col + j] = acc[i][j];
        }
    }
}

__global__ __launch_bounds__(256) void k_gemm_qkvb(const float* __restrict__ A,
                                                   const float* __restrict__ B) {
    gemm_abt_128x64(A, B, g_qkvb, NQKVB, DM);
}

// output projection writes into g_qkvb (reused as [m][1024])
__global__ __launch_bounds__(256) void k_gemm_out(const float* __restrict__ B) {
    gemm_abt_128x64(g_lo, B, g_qkvb, DM, DM);
}

// ---------------- split + activations: 1 warp per (token m, head) -------------
__global__ __launch_bounds__(256) void k_split() {
    int gw = (blockIdx.x * blockDim.x + threadIdx.x) >> 5;   // 0..131071
    int lane = threadIdx.x & 31;
    int m = gw >> 4;        // token row (l*4 + b)
    int hd = gw & 15;
    int l = m >> 2;
    int b = m & 3;
    const float* base = g_qkvb + (size_t)m * NQKVB + hd * 193;

    size_t oidx = ((size_t)(b * 16 + hd) * SLEN + l) * DH + lane;

    // q : elu+1 then sum-normalize over the 64 dims
    float x0 = base[lane], x1 = base[lane + 32];
    float e0 = x0 > 0.f ? x0 + 1.f : expf(x0);
    float e1 = x1 > 0.f ? x1 + 1.f : expf(x1);
    float s = e0 + e1;
#pragma unroll
    for (int o = 16; o > 0; o >>= 1) s += __shfl_xor_sync(0xffffffffu, s, o);
    float inv = 1.f / s;
    g_q[oidx] = e0 * inv;
    g_q[oidx + 32] = e1 * inv;

    // k
    x0 = base[64 + lane]; x1 = base[96 + lane];
    e0 = x0 > 0.f ? x0 + 1.f : expf(x0);
    e1 = x1 > 0.f ? x1 + 1.f : expf(x1);
    s = e0 + e1;
#pragma unroll
    for (int o = 16; o > 0; o >>= 1) s += __shfl_xor_sync(0xffffffffu, s, o);
    inv = 1.f / s;
    g_k[oidx] = e0 * inv;
    g_k[oidx + 32] = e1 * inv;

    // v
    g_v[oidx] = base[128 + lane];
    g_v[oidx + 32] = base[160 + lane];

    // beta (sigmoid)
    if (lane == 0) {
        float br = base[192];
        g_beta[(size_t)(b * 16 + hd) * SLEN + l] = 1.f / (1.f + expf(-br));
    }
}

// ---------------- delta-rule recurrence: 1 CTA per (b,h), 64 threads ----------
// Thread i owns row i of W (64 fp32 registers). Fuses cumsum / key_denom /
// denominator bookkeeping into the same sequential loop.
__global__ __launch_bounds__(64) void k_recur() {
    const int bh = blockIdx.x;       // 0..63 = b*16 + h
    const int tid = threadIdx.x;     // 0..63
    const int b = bh >> 4;
    const int hd = bh & 15;

    __shared__ __align__(16) float k_sh[64];
    __shared__ __align__(16) float q_sh[64];
    __shared__ __align__(16) float acc_sh[64];

    float W[64];
#pragma unroll
    for (int j = 0; j < 64; j++) W[j] = 0.f;
    acc_sh[tid] = 0.f;

    const float* __restrict__ kp = g_k + (size_t)bh * SLEN * DH;
    const float* __restrict__ qp = g_q + (size_t)bh * SLEN * DH;
    const float* __restrict__ vp = g_v + (size_t)bh * SLEN * DH;
    const float* __restrict__ bp = g_beta + (size_t)bh * SLEN;

    float kn = kp[tid], qn = qp[tid], vn = vp[tid], bn_ = bp[0];
    __syncthreads();

    for (int t = 0; t < SLEN; t++) {
        float kc = kn, qc = qn, vc = vn, bc = bn_;
        if (t + 1 < SLEN) {
            kn = kp[(size_t)(t + 1) * DH + tid];
            qn = qp[(size_t)(t + 1) * DH + tid];
            vn = vp[(size_t)(t + 1) * DH + tid];
            bn_ = bp[t + 1];
        }
        k_sh[tid] = kc;
        q_sh[tid] = qc;
        __syncthreads();

        const float4* a4 = (const float4*)acc_sh;
        const float4* k4 = (const float4*)k_sh;
        const float4* q4 = (const float4*)q_sh;

        // key_denom = <acc (pre-update), k_t>   (redundant per thread; ILP-4)
        float kdx = 0.f, kdy = 0.f, kdz = 0.f, kdw = 0.f;
#pragma unroll
        for (int j = 0; j < 16; j++) {
            float4 a = a4[j], kk = k4[j];
            kdx = fmaf(a.x, kk.x, kdx); kdy = fmaf(a.y, kk.y, kdy);
            kdz = fmaf(a.z, kk.z, kdz); kdw = fmaf(a.w, kk.w, kdw);
        }
        float kd = (kdx + kdy) + (kdz + kdw);
        if (t == 0) kd = 1.f;
        float s = 1.f / (kd + EPSF);
        float beta_eff = bc * kd;

        // v_old_i = s * <W_i, k_raw>
        float vx = 0.f, vy = 0.f, vz = 0.f, vw = 0.f;
#pragma unroll
        for (int j = 0; j < 16; j++) {
            float4 kk = k4[j];
            vx = fmaf(W[4 * j + 0], kk.x, vx);
            vy = fmaf(W[4 * j + 1], kk.y, vy);
            vz = fmaf(W[4 * j + 2], kk.z, vz);
            vw = fmaf(W[4 * j + 3], kk.w, vw);
        }
        float vo = ((vx + vy) + (vz + vw)) * s;
        float ds = beta_eff * (vc - vo) * s;   // delta_i * 1/(kd+eps)

        // W_i += ds * k_raw;  out_i = <W_i_new, q_t>   (fused)
        float ox = 0.f, oy = 0.f, oz = 0.f, ow = 0.f;
#pragma unroll
        for (int j = 0; j < 16; j++) {
            float4 kk = k4[j], qq = q4[j];
            W[4 * j + 0] = fmaf(ds, kk.x, W[4 * j + 0]);
            ox = fmaf(W[4 * j + 0], qq.x, ox);
            W[4 * j + 1] = fmaf(ds, kk.y, W[4 * j + 1]);
            oy = fmaf(W[4 * j + 1], qq.y, oy);
            W[4 * j + 2] = fmaf(ds, kk.z, W[4 * j + 2]);
            oz = fmaf(W[4 * j + 2], qq.z, oz);
            W[4 * j + 3] = fmaf(ds, kk.w, W[4 * j + 3]);
            ow = fmaf(W[4 * j + 3], qq.w, ow);
        }
        float outv = (ox + oy) + (oz + ow);

        __syncthreads();              // all kd reads of acc done
        acc_sh[tid] += kc;            // cumsum update (now includes t)
        __syncthreads();

        // denominator = <acc (post-update), q_t>
        float dx = 0.f, dy = 0.f, dz = 0.f, dw = 0.f;
#pragma unroll
        for (int j = 0; j < 16; j++) {
            float4 a = a4[j], qq = q4[j];
            dx = fmaf(a.x, qq.x, dx); dy = fmaf(a.y, qq.y, dy);
            dz = fmaf(a.z, qq.z, dz); dw = fmaf(a.w, qq.w, dw);
        }
        float den = (dx + dy) + (dz + dw);

        g_lo[((size_t)t * BSZ + b) * DM + hd * DH + tid] =
            SCALEF * outv / (den + EPSF);
        __syncthreads();              // protect k_sh/q_sh/acc for next iter
    }
}

// ---------------- residual + LayerNorm, 1 block per row -----------------------
__global__ __launch_bounds__(256) void k_ln(const float* __restrict__ hin,
                                            const float* __restrict__ gamma,
                                            const float* __restrict__ beta,
                                            float* __restrict__ out) {
    int m = blockIdx.x;
    int tid = threadIdx.x;
    const float* ar = g_qkvb + (size_t)m * DM;   // attn result (reused buffer)
    const float* hr = hin + (size_t)m * DM;

    float x[4];
    float s = 0.f;
#pragma unroll
    for (int i = 0; i < 4; i++) {
        int c = tid + i * 256;
        x[i] = ar[c] + hr[c];
        s += x[i];
    }
    __shared__ float red[8];
    int wid = tid >> 5, lane = tid & 31;
#pragma unroll
    for (int o = 16; o > 0; o >>= 1) s += __shfl_xor_sync(0xffffffffu, s, o);
    if (lane == 0) red[wid] = s;
    __syncthreads();
    float tot = 0.f;
#pragma unroll
    for (int i = 0; i < 8; i++) tot += red[i];
    float mu = tot * (1.f / (float)DM);

    float v = 0.f;
#pragma unroll
    for (int i = 0; i < 4; i++) {
        float d = x[i] - mu;
        v += d * d;
    }
#pragma unroll
    for (int o = 16; o > 0; o >>= 1) v += __shfl_xor_sync(0xffffffffu, v, o);
    __syncthreads();
    if (lane == 0) red[wid] = v;
    __syncthreads();
    float vt = 0.f;
#pragma unroll
    for (int i = 0; i < 8; i++) vt += red[i];
    float rs = rsqrtf(vt * (1.f / (float)DM) + EPSF);

#pragma unroll
    for (int i = 0; i < 4; i++) {
        int c = tid + i * 256;
        out[(size_t)m * DM + c] = (x[i] - mu) * rs * gamma[c] + beta[c];
    }
}

// ---------------- launch ------------------------------------------------------
extern "C" void kernel_launch(void* const* d_in, const int* in_sizes, int n_in,
                              void* d_out, int out_size) {
    const float* h      = (const float*)d_in[0];
    const float* w_qkvb = (const float*)d_in[1];
    const float* w_o    = (const float*)d_in[2];
    const float* ln_g   = (const float*)d_in[3];
    const float* ln_b   = (const float*)d_in[4];
    float* out = (float*)d_out;

    // qkvb projection: M=8192, N=3088, K=1024
    k_gemm_qkvb<<<dim3((NQKVB + 63) / 64, M_ROWS / 128), 256>>>(h, w_qkvb);
    // split + elu/normalize/sigmoid: 131072 warps
    k_split<<<(M_ROWS * NH) / 8, 256>>>();
    // delta-rule recurrence
    k_recur<<<64, 64>>>();
    // output projection: M=8192, N=1024, K=1024 (writes into g_qkvb)
    k_gemm_out<<<dim3(DM / 64, M_ROWS / 128), 256>>>(w_o);
    // residual + layernorm
    k_ln<<<M_ROWS, 256>>>(h, ln_g, ln_b, out);
}